// round 3
// baseline (speedup 1.0000x reference)
#include <cuda_runtime.h>
#include <cuda_bf16.h>
#include <math.h>

#define NN     46080     // total nodes
#define EE     737280    // total edges
#define BG     512       // graphs
#define NODES  90
#define EPG    (NODES*16)  // 1440 edges per graph (exact)
#define FIN    90
#define HH     128
#define HL     64
#define XCW    (3*HH)    // 384

// ---------------- device scratch (no allocations allowed) ----------------
__device__ float g_deg[NN];
__device__ int   g_cnt[NN];
__device__ int   g_cur[NN];
__device__ float g_dis[NN];
__device__ int   g_off[NN];
__device__ int   g_csrc[EE];
__device__ float g_cnorm[EE];
__device__ float g_agg[NN*HH];        // aggregated features (lda = F)
__device__ float g_xc[NN*XCW];        // [h1|h2|h3] per node; == z viewed [512,34560]
__device__ float g_acc[BG*HL];        // lin1 split-K accumulator

// ---------------- init ----------------
__global__ void k_init() {
    int i = blockIdx.x*blockDim.x + threadIdx.x;
    if (i < NN) { g_deg[i] = 1.0f; g_cnt[i] = 0; g_cur[i] = 0; }
    if (i < BG*HL) g_acc[i] = 0.0f;
}

// ---------------- degree + in-degree counts (edge_index is int32!) ----------------
__global__ void k_count(const int* __restrict__ ei, const float* __restrict__ w) {
    int e = blockIdx.x*blockDim.x + threadIdx.x;
    if (e < EE) {
        int d = ei[EE + e];
        atomicAdd(&g_deg[d], w[e]);
        atomicAdd(&g_cnt[d], 1);
    }
}

// ---------------- dis = rsqrt(deg); CSR offsets (per-graph scan) ----------------
__global__ void k_dis_off() {
    int i = blockIdx.x*blockDim.x + threadIdx.x;
    if (i < NN) g_dis[i] = rsqrtf(g_deg[i]);   // deg >= 1 always (self loop weight 1)
    if (i < BG) {
        int base = i*NODES;
        int acc  = i*EPG;
        #pragma unroll 1
        for (int n = 0; n < NODES; n++) { g_off[base+n] = acc; acc += g_cnt[base+n]; }
    }
}

// ---------------- CSR fill + edge norm ----------------
__global__ void k_fill(const int* __restrict__ ei, const float* __restrict__ w) {
    int e = blockIdx.x*blockDim.x + threadIdx.x;
    if (e < EE) {
        int s = ei[e];
        int d = ei[EE + e];
        int p = g_off[d] + atomicAdd(&g_cur[d], 1);
        g_csrc[p]  = s;
        g_cnorm[p] = g_dis[s] * w[e] * g_dis[d];
    }
}

// ---------------- aggregation: agg = A_hat @ in  (one CTA per graph) ----------------
// SRC=0: in = xin (ld = F).  SRC=1: in = g_xc + colOff (ld = XCW), device symbol
// referenced INSIDE device code only.
template<int F, int SRC>
__global__ void k_aggregate(const float* __restrict__ xin, int colOff) {
    __shared__ float sh[NODES*F];
    int g = blockIdx.x;
    if (SRC == 0) {
        const float* gin = xin + (long)g * NODES * F;
        for (int idx = threadIdx.x; idx < NODES*F; idx += blockDim.x)
            sh[idx] = gin[idx];
    } else {
        const float* gin = g_xc + (long)g * NODES * XCW + colOff;
        for (int idx = threadIdx.x; idx < NODES*F; idx += blockDim.x) {
            int r = idx / F, c = idx - r*F;
            sh[idx] = gin[r*XCW + c];
        }
    }
    __syncthreads();

    int warp = threadIdx.x >> 5, lane = threadIdx.x & 31;
    const int NFR = (F + 31) / 32;   // regs per lane (3 for 90, 4 for 128)
    for (int node = warp; node < NODES; node += (blockDim.x >> 5)) {
        int gi = g*NODES + node;
        float ds = g_dis[gi];
        float selfnm = ds * ds;
        float acc[NFR];
        #pragma unroll
        for (int j = 0; j < NFR; j++) {
            int f = lane + 32*j;
            acc[j] = (f < F) ? selfnm * sh[node*F + f] : 0.0f;
        }
        int o = g_off[gi], c = g_cnt[gi];
        for (int p = o; p < o + c; p++) {
            int sl = g_csrc[p] - g*NODES;   // local source row
            float nm = g_cnorm[p];
            #pragma unroll
            for (int j = 0; j < NFR; j++) {
                int f = lane + 32*j;
                if (f < F) acc[j] = fmaf(nm, sh[sl*F + f], acc[j]);
            }
        }
        #pragma unroll
        for (int j = 0; j < NFR; j++) {
            int f = lane + 32*j;
            if (f < F) g_agg[gi*F + f] = acc[j];
        }
    }
}

// ---------------- conv GEMM: xc[:, colOff:colOff+128] = relu(agg @ W + b) ----------------
// A = g_agg [NN x K] (lda=K), B = W [K x 128], BM=64, BN=128, BK=16, 256 thr, 8x4 micro.
template<int K>
__global__ void k_gemm_conv(const float* __restrict__ W, const float* __restrict__ b,
                            int colOff) {
    __shared__ float As[16][64];
    __shared__ float Bs[16][128];
    const int t  = threadIdx.x;
    const int tm = t >> 5;         // 0..7   (uniform per warp)
    const int tn = t & 31;         // 0..31
    const int row0 = blockIdx.x * 64;

    float acc[8][4];
    #pragma unroll
    for (int i = 0; i < 8; i++)
        #pragma unroll
        for (int j = 0; j < 4; j++) acc[i][j] = 0.0f;

    const int KT = (K + 15) / 16;
    for (int kt = 0; kt < KT; kt++) {
        int k0 = kt * 16;
        #pragma unroll
        for (int j = 0; j < 4; j++) {
            int idx = t*4 + j;          // 0..1023
            int m = idx >> 4, k = idx & 15;
            As[k][m] = (k0 + k < K) ? g_agg[(row0 + m)*K + k0 + k] : 0.0f;
        }
        #pragma unroll
        for (int j = 0; j < 8; j++) {
            int idx = t*8 + j;          // 0..2047
            int k = idx >> 7, n = idx & 127;
            Bs[k][n] = (k0 + k < K) ? W[(k0 + k)*HH + n] : 0.0f;
        }
        __syncthreads();
        #pragma unroll
        for (int k = 0; k < 16; k++) {
            float4 a0 = *(const float4*)&As[k][tm*8];
            float4 a1 = *(const float4*)&As[k][tm*8 + 4];
            float4 bv = *(const float4*)&Bs[k][tn*4];
            float av[8] = {a0.x,a0.y,a0.z,a0.w,a1.x,a1.y,a1.z,a1.w};
            float bb[4] = {bv.x,bv.y,bv.z,bv.w};
            #pragma unroll
            for (int i = 0; i < 8; i++)
                #pragma unroll
                for (int j = 0; j < 4; j++)
                    acc[i][j] = fmaf(av[i], bb[j], acc[i][j]);
        }
        __syncthreads();
    }

    float4 bias = *(const float4*)&b[tn*4];
    float bb[4] = {bias.x, bias.y, bias.z, bias.w};
    #pragma unroll
    for (int i = 0; i < 8; i++) {
        int r = row0 + tm*8 + i;
        float4 v;
        v.x = fmaxf(acc[i][0] + bb[0], 0.0f);
        v.y = fmaxf(acc[i][1] + bb[1], 0.0f);
        v.z = fmaxf(acc[i][2] + bb[2], 0.0f);
        v.w = fmaxf(acc[i][3] + bb[3], 0.0f);
        *(float4*)&g_xc[r*XCW + colOff + tn*4] = v;
    }
}

// ---------------- lin1 split-K GEMM: acc += xc([512,34560]) @ lin1_W([34560,64]) ----------------
// BM=64, BN=64, BK=16, KC=768 per CTA; grid (8, 45); 256 thr, 4x4 micro.
__global__ void k_lin1(const float* __restrict__ W) {
    __shared__ float As[16][64];
    __shared__ float Bs[16][64];
    const int t  = threadIdx.x;
    const int tm = t >> 4;         // 0..15
    const int tn = t & 15;         // 0..15
    const int row0  = blockIdx.x * 64;
    const int kbase = blockIdx.y * 768;
    const int LDA = NODES * XCW;   // 34560

    float acc[4][4];
    #pragma unroll
    for (int i = 0; i < 4; i++)
        #pragma unroll
        for (int j = 0; j < 4; j++) acc[i][j] = 0.0f;

    for (int kt = 0; kt < 48; kt++) {
        int k0 = kbase + kt*16;
        #pragma unroll
        for (int j = 0; j < 4; j++) {
            int idx = t*4 + j;
            int m = idx >> 4, k = idx & 15;
            As[k][m] = g_xc[(row0 + m)*LDA + k0 + k];
        }
        #pragma unroll
        for (int j = 0; j < 4; j++) {
            int idx = t*4 + j;
            int k = idx >> 6, n = idx & 63;
            Bs[k][n] = W[(k0 + k)*HL + n];
        }
        __syncthreads();
        #pragma unroll
        for (int k = 0; k < 16; k++) {
            float4 a = *(const float4*)&As[k][tm*4];
            float4 bv = *(const float4*)&Bs[k][tn*4];
            float av[4] = {a.x,a.y,a.z,a.w};
            float bb[4] = {bv.x,bv.y,bv.z,bv.w};
            #pragma unroll
            for (int i = 0; i < 4; i++)
                #pragma unroll
                for (int j = 0; j < 4; j++)
                    acc[i][j] = fmaf(av[i], bb[j], acc[i][j]);
        }
        __syncthreads();
    }
    #pragma unroll
    for (int i = 0; i < 4; i++)
        #pragma unroll
        for (int j = 0; j < 4; j++)
            atomicAdd(&g_acc[(row0 + tm*4 + i)*HL + tn*4 + j], acc[i][j]);
}

// ---------------- epilogue: relu -> lin2 -> log_softmax ----------------
__global__ void k_final(const float* __restrict__ b1, const float* __restrict__ W2,
                        const float* __restrict__ b2, float* __restrict__ out) {
    int g = blockIdx.x*blockDim.x + threadIdx.x;
    if (g >= BG) return;
    float l0 = b2[0], l1 = b2[1];
    #pragma unroll 8
    for (int j = 0; j < HL; j++) {
        float h = fmaxf(g_acc[g*HL + j] + b1[j], 0.0f);
        l0 = fmaf(h, W2[j*2 + 0], l0);
        l1 = fmaf(h, W2[j*2 + 1], l1);
    }
    float m = fmaxf(l0, l1);
    float lse = m + logf(expf(l0 - m) + expf(l1 - m));
    out[g*2 + 0] = l0 - lse;
    out[g*2 + 1] = l1 - lse;
}

// ---------------- launch ----------------
extern "C" void kernel_launch(void* const* d_in, const int* in_sizes, int n_in,
                              void* d_out, int out_size) {
    const float* x      = (const float*)d_in[0];
    const float* eattr  = (const float*)d_in[1];
    const float* W1     = (const float*)d_in[2];
    const float* b1     = (const float*)d_in[3];
    const float* W2     = (const float*)d_in[4];
    const float* b2     = (const float*)d_in[5];
    const float* W3     = (const float*)d_in[6];
    const float* b3     = (const float*)d_in[7];
    const float* lin1W  = (const float*)d_in[8];
    const float* lin1b  = (const float*)d_in[9];
    const float* lin2W  = (const float*)d_in[10];
    const float* lin2b  = (const float*)d_in[11];
    const int*   eidx   = (const int*)d_in[12];   // int32 (JAX x64 disabled)
    float*       out    = (float*)d_out;

    k_init<<<(NN + 255)/256, 256>>>();
    k_count<<<(EE + 255)/256, 256>>>(eidx, eattr);
    k_dis_off<<<(NN + 255)/256, 256>>>();
    k_fill<<<(EE + 255)/256, 256>>>(eidx, eattr);

    // layer 1: aggregate x (F=90), GEMM 90->128, relu -> xc[:,0:128]
    k_aggregate<FIN, 0><<<BG, 256>>>(x, 0);
    k_gemm_conv<FIN><<<NN/64, 256>>>(W1, b1, 0);

    // layer 2: aggregate h1 (F=128, from g_xc col 0), GEMM 128->128 -> xc[:,128:256]
    k_aggregate<HH, 1><<<BG, 256>>>(nullptr, 0);
    k_gemm_conv<HH><<<NN/64, 256>>>(W2, b2, HH);

    // layer 3: aggregate h2 (from g_xc col 128) -> xc[:,256:384]
    k_aggregate<HH, 1><<<BG, 256>>>(nullptr, HH);
    k_gemm_conv<HH><<<NN/64, 256>>>(W3, b3, 2*HH);

    // lin1 split-K, then fused relu/lin2/log_softmax
    dim3 g1(BG/64, 45);
    k_lin1<<<g1, 256>>>(lin1W);
    k_final<<<(BG + 255)/256, 256>>>(lin1b, lin2W, lin2b, out);
}